// round 5
// baseline (speedup 1.0000x reference)
#include <cuda_runtime.h>

// Problem constants
#define HH 512
#define WW 512
#define NCH 32            // B*C = 8*4
#define HW (HH * WW)
#define KIT 10

// Tile config
#define TW 128
#define TH 16
#define SW (TW + 2)
#define SH (TH + 2)

// Scratch (static device globals — no allocation)
__device__ float    g_buf[2][NCH * HW];          // ping-pong raw erosion fields (64 MB)
__device__ unsigned g_minbits[KIT][NCH];
__device__ unsigned g_maxbits[KIT][NCH];
__device__ double   g_sum[KIT][NCH];

__global__ void init_stats_kernel() {
    int i = threadIdx.x;
    if (i < KIT * NCH) {
        ((unsigned*)g_minbits)[i] = 0x7f800000u;  // +inf
        ((unsigned*)g_maxbits)[i] = 0u;           // erosion >= 0
        ((double*)g_sum)[i] = 0.0;
    }
}

// One erosion iteration:
//  - FIRST=true : input field = (pred - onehot(target))^2 computed on the fly
//  - FIRST=false: input field = affine(raw erosion of prev iter)  [deferred normalization]
//  conv (3x3 cross, *0.2, zero pad) -> relu(x - 0.5) -> write raw erosion,
//  reduce per-channel min/max/sum of the raw erosion.
template <bool FIRST>
__global__ void erode_step_kernel(const float* __restrict__ pred,
                                  const int* __restrict__ tgt,  // int32 (JAX x64 off)
                                  int iter, int src) {
    __shared__ float tile[SH][SW];
    __shared__ float rmin[8], rmax[8], rsum[8];

    const int ch = blockIdx.z;
    const int x0 = blockIdx.x * TW - 1;
    const int y0 = blockIdx.y * TH - 1;
    const int tid = threadIdx.x;

    // Per-channel affine from previous iteration's raw stats
    float mn = 0.0f, inv = 1.0f;
    if (!FIRST) {
        float a = __uint_as_float(g_minbits[iter - 1][ch]);
        float b = __uint_as_float(g_maxbits[iter - 1][ch]);
        float d = b - a;
        if (d != 0.0f) { mn = a; inv = 1.0f / d; }
    }

    const float* __restrict__ in  = g_buf[src] + (size_t)ch * HW;
    float* __restrict__ out       = g_buf[FIRST ? 0 : (src ^ 1)] + (size_t)ch * HW;
    const float* __restrict__ pch = FIRST ? (pred + (size_t)ch * HW) : nullptr;
    const int* __restrict__ tch   = FIRST ? (tgt + (size_t)(ch >> 2) * HW) : nullptr;
    const int cls = ch & 3;

    // Cooperative halo-tile load (out-of-bounds -> 0, i.e. zero padding of the
    // NORMALIZED field).
    for (int i = tid; i < SH * SW; i += blockDim.x) {
        int ly = i / SW, lx = i - ly * SW;
        int gy = y0 + ly, gx = x0 + lx;
        float v = 0.0f;
        if ((unsigned)gy < HH && (unsigned)gx < WW) {
            int idx = gy * WW + gx;
            if (FIRST) {
                float p  = pch[idx];
                float oh = (tch[idx] == cls) ? 1.0f : 0.0f;
                float dd = p - oh;
                v = dd * dd;
            } else {
                v = (in[idx] - mn) * inv;
            }
        }
        ((float*)tile)[i] = v;
    }
    __syncthreads();

    const int tx  = tid & (TW - 1);
    const int tyb = tid >> 7;  // 0..1

    float lmin = __uint_as_float(0x7f800000u);
    float lmax = 0.0f;
    float lsum = 0.0f;

#pragma unroll
    for (int r = 0; r < TH / 2; ++r) {
        int ty = tyb * (TH / 2) + r;
        float c = tile[ty + 1][tx + 1];
        float s = c + tile[ty][tx + 1] + tile[ty + 2][tx + 1]
                    + tile[ty + 1][tx] + tile[ty + 1][tx + 2];
        float e = fmaxf(0.2f * s - 0.5f, 0.0f);
        out[(y0 + 1 + ty) * WW + (x0 + 1 + tx)] = e;
        lmin = fminf(lmin, e);
        lmax = fmaxf(lmax, e);
        lsum += e;
    }

    // Warp reduce
#pragma unroll
    for (int o = 16; o; o >>= 1) {
        lmin = fminf(lmin, __shfl_xor_sync(0xffffffffu, lmin, o));
        lmax = fmaxf(lmax, __shfl_xor_sync(0xffffffffu, lmax, o));
        lsum += __shfl_xor_sync(0xffffffffu, lsum, o);
    }
    if ((tid & 31) == 0) {
        int w = tid >> 5;
        rmin[w] = lmin; rmax[w] = lmax; rsum[w] = lsum;
    }
    __syncthreads();
    if (tid == 0) {
        float bm = rmax[0], bn = rmin[0], bs = rsum[0];
#pragma unroll
        for (int i = 1; i < 8; ++i) {
            bm = fmaxf(bm, rmax[i]);
            bn = fminf(bn, rmin[i]);
            bs += rsum[i];
        }
        // erosion >= 0  =>  float bit pattern order == unsigned order
        atomicMax(&g_maxbits[iter][ch], __float_as_uint(bm));
        atomicMin(&g_minbits[iter][ch], __float_as_uint(bn));
        atomicAdd(&g_sum[iter][ch], (double)bs);
    }
}

__global__ void finalize_kernel(float* __restrict__ outp) {
    if (threadIdx.x == 0) {
        double total = 0.0;
        for (int k = 0; k < KIT; ++k) {
            double w = (double)(k + 1) * (double)(k + 1);  // (k+1)^ALPHA, ALPHA=2
            for (int c = 0; c < NCH; ++c) {
                float mnf = __uint_as_float(g_minbits[k][c]);
                float mxf = __uint_as_float(g_maxbits[k][c]);
                double S  = g_sum[k][c];
                float d   = mxf - mnf;
                double ns = (d != 0.0f)
                          ? (S - (double)HW * (double)mnf) / (double)d
                          : S;
                total += w * ns;
            }
        }
        outp[0] = (float)(total / (double)((double)NCH * (double)HW));
    }
}

extern "C" void kernel_launch(void* const* d_in, const int* in_sizes, int n_in,
                              void* d_out, int out_size) {
    const float* pred = (const float*)d_in[0];
    const int* tgt    = (const int*)d_in[1];

    init_stats_kernel<<<1, 512>>>();

    dim3 block(256);
    dim3 grid(WW / TW, HH / TH, NCH);  // (4, 32, 32)

    // iter 0: bound = (pred - onehot)^2 computed on the fly, writes g_buf[0]
    erode_step_kernel<true><<<grid, block>>>(pred, tgt, 0, 0);

    // iters 1..9: ping-pong, normalization deferred to load
    int src = 0;
    for (int k = 1; k < KIT; ++k) {
        erode_step_kernel<false><<<grid, block>>>(nullptr, nullptr, k, src);
        src ^= 1;
    }

    finalize_kernel<<<1, 32>>>((float*)d_out);
}

// round 8
// speedup vs baseline: 1.4958x; 1.4958x over previous
#include <cuda_runtime.h>

#define HH 512
#define WW 512
#define NCH 32            // B*C = 8*4
#define HW (HH * WW)
#define KIT 10

// Scratch (static device globals — no allocation)
__device__ float    g_buf[2][NCH * HW];          // ping-pong raw erosion fields
__device__ unsigned g_minbits[KIT][NCH];
__device__ unsigned g_maxbits[KIT][NCH];
__device__ double   g_sum[KIT][NCH];

__global__ void init_stats_kernel() {
    int i = threadIdx.x;
    if (i < KIT * NCH) {
        ((unsigned*)g_minbits)[i] = 0x7f800000u;  // +inf
        ((unsigned*)g_maxbits)[i] = 0u;           // erosion >= 0
        ((double*)g_sum)[i] = 0.0;
    }
}

// One erosion iteration, register-rolling 4x4 patch per thread, no smem tile.
//
// Deferred-normalization identity: with norm(x) = (x - mn)*inv and zero padding
// of the NORMALIZED field,
//   0.2 * sum_{present taps} norm(x_i) - 0.5
//     = (0.2*inv) * S_raw - n * (0.2*inv*mn) - 0.5,
// where S_raw sums the present raw taps (OOB loads return raw 0, contributing
// nothing) and n is the number of in-bounds taps. So NO per-load affine at all.
//
// FIRST=true: the input field is bound=(pred-onehot)^2 (mn=0, inv=1).
// WRITE=false (final iter): the raw field is never read again; stats only.
template <bool FIRST, bool WRITE>
__global__ void __launch_bounds__(256)
erode_step_kernel(const float* __restrict__ pred,
                  const int* __restrict__ tgt,
                  int iter, int src) {
    __shared__ float rmin[8], rmax[8], rsum[8];

    const int ch    = blockIdx.z;
    const int tid   = threadIdx.x;
    const int strip = tid & 127;            // 128 x-strips of 4 cols
    const int rg    = tid >> 7;             // 2 row-groups of 4 rows
    const int x0    = strip * 4;
    const int y0    = blockIdx.y * 8 + rg * 4;

    float mn = 0.0f, inv = 1.0f;
    if (!FIRST) {
        float a = __uint_as_float(g_minbits[iter - 1][ch]);
        float b = __uint_as_float(g_maxbits[iter - 1][ch]);
        float d = b - a;
        if (d != 0.0f) { mn = a; inv = 1.0f / d; }
    }
    const float A     = 0.2f * inv;
    const float DELTA = 0.2f * inv * mn;    // per-present-tap correction

    const float* __restrict__ in  = g_buf[src] + (size_t)ch * HW;
    float* __restrict__ out       = g_buf[FIRST ? 0 : (src ^ 1)] + (size_t)ch * HW;
    const float* __restrict__ pch = pred + (size_t)ch * HW;
    const int* __restrict__ tch   = tgt + (size_t)(ch >> 2) * HW;
    const int cls = ch & 3;

    // ---- row loaders (raw field values; OOB -> 0) ----
    auto load4 = [&](int y) -> float4 {
        if ((unsigned)y >= HH) return make_float4(0.f, 0.f, 0.f, 0.f);
        if (FIRST) {
            float4 p = *(const float4*)(pch + y * WW + x0);
            int4   t = *(const int4*)(tch + y * WW + x0);
            float4 v;
            v.x = p.x - (t.x == cls ? 1.0f : 0.0f); v.x *= v.x;
            v.y = p.y - (t.y == cls ? 1.0f : 0.0f); v.y *= v.y;
            v.z = p.z - (t.z == cls ? 1.0f : 0.0f); v.z *= v.z;
            v.w = p.w - (t.w == cls ? 1.0f : 0.0f); v.w *= v.w;
            return v;
        }
        return *(const float4*)(in + y * WW + x0);
    };
    auto load1 = [&](int y, int x) -> float {
        if ((unsigned)x >= WW) return 0.0f;  // y always in range at call sites
        if (FIRST) {
            float p = pch[y * WW + x];
            float v = p - (tch[y * WW + x] == cls ? 1.0f : 0.0f);
            return v * v;
        }
        return in[y * WW + x];
    };

    float4 rv[6];
#pragma unroll
    for (int i = 0; i < 6; ++i) rv[i] = load4(y0 - 1 + i);

    float lmin = __uint_as_float(0x7f800000u);
    float lmax = 0.0f;
    float lsum = 0.0f;

    const float mx0 = (x0 == 0) ? 1.0f : 0.0f;         // left tap missing (elem 0)
    const float mx3 = (x0 + 3 == WW - 1) ? 1.0f : 0.0f; // right tap missing (elem 3)

#pragma unroll
    for (int i = 0; i < 4; ++i) {
        const int y = y0 + i;
        const float4 c = rv[i + 1], u = rv[i], d = rv[i + 2];
        const float l = load1(y, x0 - 1);
        const float r = load1(y, x0 + 4);
        const float my = (y == 0 || y == HH - 1) ? 1.0f : 0.0f;

        const float S0 = c.x + u.x + d.x + l   + c.y;
        const float S1 = c.y + u.y + d.y + c.x + c.z;
        const float S2 = c.z + u.z + d.z + c.y + c.w;
        const float S3 = c.w + u.w + d.w + c.z + r;

        const float bi = my * DELTA + 0.5f;            // interior bias part
        const float e0 = fmaxf(fmaf(A, S0, (5.0f - mx0) * DELTA * 0.0f
                                           - ((5.0f - my - mx0) * DELTA + 0.5f)), 0.0f);
        const float e1 = fmaxf(fmaf(A, S1, -((5.0f - my) * DELTA + 0.5f)), 0.0f);
        const float e2 = fmaxf(fmaf(A, S2, -((5.0f - my) * DELTA + 0.5f)), 0.0f);
        const float e3 = fmaxf(fmaf(A, S3, -((5.0f - my - mx3) * DELTA + 0.5f)), 0.0f);
        (void)bi;

        if (WRITE)
            *(float4*)(out + y * WW + x0) = make_float4(e0, e1, e2, e3);

        lmin = fminf(lmin, fminf(fminf(e0, e1), fminf(e2, e3)));
        lmax = fmaxf(lmax, fmaxf(fmaxf(e0, e1), fmaxf(e2, e3)));
        lsum += (e0 + e1) + (e2 + e3);
    }

    // ---- reduction: warp -> block -> global atomics ----
#pragma unroll
    for (int o = 16; o; o >>= 1) {
        lmin = fminf(lmin, __shfl_xor_sync(0xffffffffu, lmin, o));
        lmax = fmaxf(lmax, __shfl_xor_sync(0xffffffffu, lmax, o));
        lsum += __shfl_xor_sync(0xffffffffu, lsum, o);
    }
    if ((tid & 31) == 0) {
        int w = tid >> 5;
        rmin[w] = lmin; rmax[w] = lmax; rsum[w] = lsum;
    }
    __syncthreads();
    if (tid == 0) {
        float bm = rmax[0], bn = rmin[0];
        float bs = rsum[0];
#pragma unroll
        for (int i = 1; i < 8; ++i) {
            bm = fmaxf(bm, rmax[i]);
            bn = fminf(bn, rmin[i]);
            bs += rsum[i];
        }
        atomicMax(&g_maxbits[iter][ch], __float_as_uint(bm));
        atomicMin(&g_minbits[iter][ch], __float_as_uint(bn));
        atomicAdd(&g_sum[iter][ch], (double)bs);
    }
}

__global__ void finalize_kernel(float* __restrict__ outp) {
    if (threadIdx.x == 0) {
        double total = 0.0;
        for (int k = 0; k < KIT; ++k) {
            double w = (double)(k + 1) * (double)(k + 1);  // (k+1)^2
            for (int c = 0; c < NCH; ++c) {
                float mnf = __uint_as_float(g_minbits[k][c]);
                float mxf = __uint_as_float(g_maxbits[k][c]);
                double S  = g_sum[k][c];
                float d   = mxf - mnf;
                double ns = (d != 0.0f)
                          ? (S - (double)HW * (double)mnf) / (double)d
                          : S;
                total += w * ns;
            }
        }
        outp[0] = (float)(total / (double)((double)NCH * (double)HW));
    }
}

extern "C" void kernel_launch(void* const* d_in, const int* in_sizes, int n_in,
                              void* d_out, int out_size) {
    const float* pred = (const float*)d_in[0];
    const int* tgt    = (const int*)d_in[1];

    init_stats_kernel<<<1, 512>>>();

    dim3 block(256);
    dim3 grid(1, HH / 8, NCH);  // (1, 64, 32): block covers 512 cols x 8 rows

    // iter 0: bound = (pred - onehot)^2 computed on the fly, writes g_buf[0]
    erode_step_kernel<true, true><<<grid, block>>>(pred, tgt, 0, 0);

    // iters 1..8: ping-pong, normalization pushed through the conv
    int src = 0;
    for (int k = 1; k < KIT - 1; ++k) {
        erode_step_kernel<false, true><<<grid, block>>>(pred, tgt, k, src);
        src ^= 1;
    }
    // iter 9: stats only, no field store
    erode_step_kernel<false, false><<<grid, block>>>(pred, tgt, KIT - 1, src);

    finalize_kernel<<<1, 32>>>((float*)d_out);
}

// round 9
// speedup vs baseline: 1.4985x; 1.0018x over previous
#include <cuda_runtime.h>

#define HH 512
#define WW 512
#define NCH 32            // B*C = 8*4
#define HW (HH * WW)
#define KIT 10

// Scratch (static device globals — no allocation)
__device__ float    g_buf[2][NCH * HW];          // ping-pong raw erosion fields
__device__ unsigned g_minbits[KIT][NCH];
__device__ unsigned g_maxbits[KIT][NCH];
__device__ double   g_sum[KIT][NCH];

__global__ void init_stats_kernel() {
    int i = threadIdx.x;
    if (i < KIT * NCH) {
        ((unsigned*)g_minbits)[i] = 0x7f800000u;  // +inf
        ((unsigned*)g_maxbits)[i] = 0u;           // erosion >= 0
        ((double*)g_sum)[i] = 0.0;
    }
}

// One erosion iteration, register-rolling 4x4 patch per thread, no smem tile.
//
// Deferred-normalization identity: with norm(x) = (x - mn)*inv and zero padding
// of the NORMALIZED field,
//   0.2 * sum_{present taps} norm(x_i) - 0.5
//     = (0.2*inv) * S_raw - n * (0.2*inv*mn) - 0.5,
// where S_raw sums the present raw taps (OOB loads return raw 0, contributing
// nothing) and n is the number of in-bounds taps. So NO per-load affine at all.
//
// FIRST=true: the input field is bound=(pred-onehot)^2 (mn=0, inv=1).
// WRITE=false (final iter): the raw field is never read again; stats only.
template <bool FIRST, bool WRITE>
__global__ void __launch_bounds__(256)
erode_step_kernel(const float* __restrict__ pred,
                  const int* __restrict__ tgt,
                  int iter, int src) {
    __shared__ float rmin[8], rmax[8], rsum[8];

    const int ch    = blockIdx.z;
    const int tid   = threadIdx.x;
    const int strip = tid & 127;            // 128 x-strips of 4 cols
    const int rg    = tid >> 7;             // 2 row-groups of 4 rows
    const int x0    = strip * 4;
    const int y0    = blockIdx.y * 8 + rg * 4;

    float mn = 0.0f, inv = 1.0f;
    if (!FIRST) {
        float a = __uint_as_float(g_minbits[iter - 1][ch]);
        float b = __uint_as_float(g_maxbits[iter - 1][ch]);
        float d = b - a;
        if (d != 0.0f) { mn = a; inv = 1.0f / d; }
    }
    const float A     = 0.2f * inv;
    const float DELTA = 0.2f * inv * mn;    // per-present-tap correction

    const float* __restrict__ in  = g_buf[src] + (size_t)ch * HW;
    float* __restrict__ out       = g_buf[FIRST ? 0 : (src ^ 1)] + (size_t)ch * HW;
    const float* __restrict__ pch = pred + (size_t)ch * HW;
    const int* __restrict__ tch   = tgt + (size_t)(ch >> 2) * HW;
    const int cls = ch & 3;

    // ---- row loaders (raw field values; OOB -> 0) ----
    auto load4 = [&](int y) -> float4 {
        if ((unsigned)y >= HH) return make_float4(0.f, 0.f, 0.f, 0.f);
        if (FIRST) {
            float4 p = *(const float4*)(pch + y * WW + x0);
            int4   t = *(const int4*)(tch + y * WW + x0);
            float4 v;
            v.x = p.x - (t.x == cls ? 1.0f : 0.0f); v.x *= v.x;
            v.y = p.y - (t.y == cls ? 1.0f : 0.0f); v.y *= v.y;
            v.z = p.z - (t.z == cls ? 1.0f : 0.0f); v.z *= v.z;
            v.w = p.w - (t.w == cls ? 1.0f : 0.0f); v.w *= v.w;
            return v;
        }
        return *(const float4*)(in + y * WW + x0);
    };
    auto load1 = [&](int y, int x) -> float {
        if ((unsigned)x >= WW) return 0.0f;  // y always in range at call sites
        if (FIRST) {
            float p = pch[y * WW + x];
            float v = p - (tch[y * WW + x] == cls ? 1.0f : 0.0f);
            return v * v;
        }
        return in[y * WW + x];
    };

    float4 rv[6];
#pragma unroll
    for (int i = 0; i < 6; ++i) rv[i] = load4(y0 - 1 + i);

    float lmin = __uint_as_float(0x7f800000u);
    float lmax = 0.0f;
    float lsum = 0.0f;

    const float mx0 = (x0 == 0) ? 1.0f : 0.0f;         // left tap missing (elem 0)
    const float mx3 = (x0 + 3 == WW - 1) ? 1.0f : 0.0f; // right tap missing (elem 3)

#pragma unroll
    for (int i = 0; i < 4; ++i) {
        const int y = y0 + i;
        const float4 c = rv[i + 1], u = rv[i], d = rv[i + 2];
        const float l = load1(y, x0 - 1);
        const float r = load1(y, x0 + 4);
        const float my = (y == 0 || y == HH - 1) ? 1.0f : 0.0f;

        const float S0 = c.x + u.x + d.x + l   + c.y;
        const float S1 = c.y + u.y + d.y + c.x + c.z;
        const float S2 = c.z + u.z + d.z + c.y + c.w;
        const float S3 = c.w + u.w + d.w + c.z + r;

        const float bi = my * DELTA + 0.5f;            // interior bias part
        const float e0 = fmaxf(fmaf(A, S0, (5.0f - mx0) * DELTA * 0.0f
                                           - ((5.0f - my - mx0) * DELTA + 0.5f)), 0.0f);
        const float e1 = fmaxf(fmaf(A, S1, -((5.0f - my) * DELTA + 0.5f)), 0.0f);
        const float e2 = fmaxf(fmaf(A, S2, -((5.0f - my) * DELTA + 0.5f)), 0.0f);
        const float e3 = fmaxf(fmaf(A, S3, -((5.0f - my - mx3) * DELTA + 0.5f)), 0.0f);
        (void)bi;

        if (WRITE)
            *(float4*)(out + y * WW + x0) = make_float4(e0, e1, e2, e3);

        lmin = fminf(lmin, fminf(fminf(e0, e1), fminf(e2, e3)));
        lmax = fmaxf(lmax, fmaxf(fmaxf(e0, e1), fmaxf(e2, e3)));
        lsum += (e0 + e1) + (e2 + e3);
    }

    // ---- reduction: warp -> block -> global atomics ----
#pragma unroll
    for (int o = 16; o; o >>= 1) {
        lmin = fminf(lmin, __shfl_xor_sync(0xffffffffu, lmin, o));
        lmax = fmaxf(lmax, __shfl_xor_sync(0xffffffffu, lmax, o));
        lsum += __shfl_xor_sync(0xffffffffu, lsum, o);
    }
    if ((tid & 31) == 0) {
        int w = tid >> 5;
        rmin[w] = lmin; rmax[w] = lmax; rsum[w] = lsum;
    }
    __syncthreads();
    if (tid == 0) {
        float bm = rmax[0], bn = rmin[0];
        float bs = rsum[0];
#pragma unroll
        for (int i = 1; i < 8; ++i) {
            bm = fmaxf(bm, rmax[i]);
            bn = fminf(bn, rmin[i]);
            bs += rsum[i];
        }
        atomicMax(&g_maxbits[iter][ch], __float_as_uint(bm));
        atomicMin(&g_minbits[iter][ch], __float_as_uint(bn));
        atomicAdd(&g_sum[iter][ch], (double)bs);
    }
}

__global__ void finalize_kernel(float* __restrict__ outp) {
    if (threadIdx.x == 0) {
        double total = 0.0;
        for (int k = 0; k < KIT; ++k) {
            double w = (double)(k + 1) * (double)(k + 1);  // (k+1)^2
            for (int c = 0; c < NCH; ++c) {
                float mnf = __uint_as_float(g_minbits[k][c]);
                float mxf = __uint_as_float(g_maxbits[k][c]);
                double S  = g_sum[k][c];
                float d   = mxf - mnf;
                double ns = (d != 0.0f)
                          ? (S - (double)HW * (double)mnf) / (double)d
                          : S;
                total += w * ns;
            }
        }
        outp[0] = (float)(total / (double)((double)NCH * (double)HW));
    }
}

extern "C" void kernel_launch(void* const* d_in, const int* in_sizes, int n_in,
                              void* d_out, int out_size) {
    const float* pred = (const float*)d_in[0];
    const int* tgt    = (const int*)d_in[1];

    init_stats_kernel<<<1, 512>>>();

    dim3 block(256);
    dim3 grid(1, HH / 8, NCH);  // (1, 64, 32): block covers 512 cols x 8 rows

    // iter 0: bound = (pred - onehot)^2 computed on the fly, writes g_buf[0]
    erode_step_kernel<true, true><<<grid, block>>>(pred, tgt, 0, 0);

    // iters 1..8: ping-pong, normalization pushed through the conv
    int src = 0;
    for (int k = 1; k < KIT - 1; ++k) {
        erode_step_kernel<false, true><<<grid, block>>>(pred, tgt, k, src);
        src ^= 1;
    }
    // iter 9: stats only, no field store
    erode_step_kernel<false, false><<<grid, block>>>(pred, tgt, KIT - 1, src);

    finalize_kernel<<<1, 32>>>((float*)d_out);
}

// round 10
// speedup vs baseline: 1.6659x; 1.1117x over previous
#include <cuda_runtime.h>

#define HH 512
#define WW 512
#define NCH 32            // B*C = 8*4
#define HW (HH * WW)
#define KIT 10

// Scratch (static device globals — no allocation)
__device__ float    g_buf[2][NCH * HW];          // ping-pong raw erosion fields
__device__ unsigned g_minbits[KIT][NCH];
__device__ unsigned g_maxbits[KIT][NCH];
__device__ double   g_sum[KIT][NCH];

__global__ void init_stats_kernel() {
    int i = threadIdx.x;
    if (i < KIT * NCH) {
        ((unsigned*)g_minbits)[i] = 0x7f800000u;  // +inf
        ((unsigned*)g_maxbits)[i] = 0u;           // erosion >= 0
        ((double*)g_sum)[i] = 0.0;
    }
}

// One erosion iteration. Each thread: 4 cols x 8 rows, rolling 3-row window.
// Horizontal halo via warp shuffle (lanes own adjacent 4-col strips).
//
// Deferred-normalization identity: with norm(x) = (x - mn)*inv and zero padding
// of the NORMALIZED field,
//   0.2 * sum_{present taps} norm(x_i) - 0.5
//     = (0.2*inv)*S_raw - (n_present * 0.2*inv*mn + 0.5)
// so raw values flow through the conv untouched; per-output bias only depends
// on how many taps fall inside the image.
template <bool FIRST, bool WRITE>
__global__ void __launch_bounds__(256, 8)
erode_step_kernel(const float* __restrict__ pred,
                  const int* __restrict__ tgt,
                  int iter, int src) {
    __shared__ float rmin[8], rmax[8], rsum[8];

    const int ch     = blockIdx.z;
    const int tid    = threadIdx.x;
    const int lane   = tid & 31;
    const int warp   = tid >> 5;
    const int warp_x = warp & 3;             // 4 warps across x (128 cols each)
    const int warp_y = warp >> 2;            // 2 warps across y (8 rows each)
    const int x0     = warp_x * 128 + lane * 4;
    const int y0     = blockIdx.y * 16 + warp_y * 8;

    float mn = 0.0f, inv = 1.0f;
    if (!FIRST) {
        float a = __uint_as_float(g_minbits[iter - 1][ch]);
        float b = __uint_as_float(g_maxbits[iter - 1][ch]);
        float d = b - a;
        if (d != 0.0f) { mn = a; inv = 1.0f / d; }
    }
    const float A     = 0.2f * inv;
    const float DELTA = 0.2f * inv * mn;           // per-present-tap correction
    const float BINT  = -(5.0f * DELTA + 0.5f);    // all-5-taps bias

    const float* __restrict__ in  = g_buf[src] + (size_t)ch * HW;
    float* __restrict__ out       = g_buf[FIRST ? 0 : (src ^ 1)] + (size_t)ch * HW;
    const float* __restrict__ pch = pred + (size_t)ch * HW;
    const int* __restrict__ tch   = tgt + (size_t)(ch >> 2) * HW;
    const int cls = ch & 3;

    auto load4 = [&](int y) -> float4 {
        if ((unsigned)y >= HH) return make_float4(0.f, 0.f, 0.f, 0.f);
        if (FIRST) {
            float4 p = *(const float4*)(pch + y * WW + x0);
            int4   t = *(const int4*)(tch + y * WW + x0);
            float4 v;
            v.x = p.x - (t.x == cls ? 1.0f : 0.0f); v.x *= v.x;
            v.y = p.y - (t.y == cls ? 1.0f : 0.0f); v.y *= v.y;
            v.z = p.z - (t.z == cls ? 1.0f : 0.0f); v.z *= v.z;
            v.w = p.w - (t.w == cls ? 1.0f : 0.0f); v.w *= v.w;
            return v;
        }
        return *(const float4*)(in + y * WW + x0);
    };
    auto load1 = [&](int y, int x) -> float {      // x known in-bounds at call sites
        if (FIRST) {
            float p = pch[y * WW + x];
            float v = p - (tch[y * WW + x] == cls ? 1.0f : 0.0f);
            return v * v;
        }
        return in[y * WW + x];
    };

    // Tap-missing flags for the global image edges (constant per thread)
    const bool left_edge  = (x0 == 0);             // elem 0 has no left tap
    const bool right_edge = (x0 + 3 == WW - 1);    // elem 3 has no right tap
    const float mx0 = left_edge  ? DELTA : 0.0f;
    const float mx3 = right_edge ? DELTA : 0.0f;
    const bool need_l = (lane == 0)  && !left_edge;   // cross-warp left scalar
    const bool need_r = (lane == 31) && !right_edge;  // cross-warp right scalar

    float4 u = load4(y0 - 1);
    float4 c = load4(y0);

    float lmin = __uint_as_float(0x7f800000u);
    float lmax = 0.0f;
    float lsum = 0.0f;

#pragma unroll
    for (int i = 0; i < 8; ++i) {
        const int y = y0 + i;
        const float4 d = load4(y + 1);

        // horizontal halo: neighbor lanes' edge elements
        float l = __shfl_up_sync(0xffffffffu, c.w, 1);
        float r = __shfl_down_sync(0xffffffffu, c.x, 1);
        if (need_l) l = load1(y, x0 - 1);
        if (need_r) r = load1(y, x0 + 4);
        if (left_edge)  l = 0.0f;
        if (right_edge) r = 0.0f;

        const float S0 = (c.x + u.x) + (d.x + l)   + c.y;
        const float S1 = (c.y + u.y) + (d.y + c.x) + c.z;
        const float S2 = (c.z + u.z) + (d.z + c.y) + c.w;
        const float S3 = (c.w + u.w) + (d.w + c.z) + r;

        const float b  = (y == 0 || y == HH - 1) ? (BINT + DELTA) : BINT;
        const float e0 = fmaxf(fmaf(A, S0, b + mx0), 0.0f);
        const float e1 = fmaxf(fmaf(A, S1, b), 0.0f);
        const float e2 = fmaxf(fmaf(A, S2, b), 0.0f);
        const float e3 = fmaxf(fmaf(A, S3, b + mx3), 0.0f);

        if (WRITE)
            *(float4*)(out + y * WW + x0) = make_float4(e0, e1, e2, e3);

        lmin = fminf(lmin, fminf(fminf(e0, e1), fminf(e2, e3)));
        lmax = fmaxf(lmax, fmaxf(fmaxf(e0, e1), fmaxf(e2, e3)));
        lsum += (e0 + e1) + (e2 + e3);

        u = c; c = d;
    }

    // ---- reduction: warp -> block -> global atomics ----
#pragma unroll
    for (int o = 16; o; o >>= 1) {
        lmin = fminf(lmin, __shfl_xor_sync(0xffffffffu, lmin, o));
        lmax = fmaxf(lmax, __shfl_xor_sync(0xffffffffu, lmax, o));
        lsum += __shfl_xor_sync(0xffffffffu, lsum, o);
    }
    if (lane == 0) {
        rmin[warp] = lmin; rmax[warp] = lmax; rsum[warp] = lsum;
    }
    __syncthreads();
    if (tid == 0) {
        float bm = rmax[0], bn = rmin[0];
        float bs = rsum[0];
#pragma unroll
        for (int i = 1; i < 8; ++i) {
            bm = fmaxf(bm, rmax[i]);
            bn = fminf(bn, rmin[i]);
            bs += rsum[i];
        }
        atomicMax(&g_maxbits[iter][ch], __float_as_uint(bm));
        atomicMin(&g_minbits[iter][ch], __float_as_uint(bn));
        atomicAdd(&g_sum[iter][ch], (double)bs);
    }
}

__global__ void finalize_kernel(float* __restrict__ outp) {
    if (threadIdx.x == 0) {
        double total = 0.0;
        for (int k = 0; k < KIT; ++k) {
            double w = (double)(k + 1) * (double)(k + 1);  // (k+1)^2
            for (int c = 0; c < NCH; ++c) {
                float mnf = __uint_as_float(g_minbits[k][c]);
                float mxf = __uint_as_float(g_maxbits[k][c]);
                double S  = g_sum[k][c];
                float d   = mxf - mnf;
                double ns = (d != 0.0f)
                          ? (S - (double)HW * (double)mnf) / (double)d
                          : S;
                total += w * ns;
            }
        }
        outp[0] = (float)(total / (double)((double)NCH * (double)HW));
    }
}

extern "C" void kernel_launch(void* const* d_in, const int* in_sizes, int n_in,
                              void* d_out, int out_size) {
    const float* pred = (const float*)d_in[0];
    const int* tgt    = (const int*)d_in[1];

    init_stats_kernel<<<1, 512>>>();

    dim3 block(256);
    dim3 grid(1, HH / 16, NCH);  // (1, 32, 32): block covers 512 cols x 16 rows

    // iter 0: bound = (pred - onehot)^2 computed on the fly, writes g_buf[0]
    erode_step_kernel<true, true><<<grid, block>>>(pred, tgt, 0, 0);

    // iters 1..8: ping-pong, normalization pushed through the conv
    int src = 0;
    for (int k = 1; k < KIT - 1; ++k) {
        erode_step_kernel<false, true><<<grid, block>>>(pred, tgt, k, src);
        src ^= 1;
    }
    // iter 9: stats only, no field store
    erode_step_kernel<false, false><<<grid, block>>>(pred, tgt, KIT - 1, src);

    finalize_kernel<<<1, 32>>>((float*)d_out);
}